// round 15
// baseline (speedup 1.0000x reference)
#include <cuda_runtime.h>

#define BB 128
#define TT 100
#define HH 512

// ---------------- scratch (device globals; no runtime alloc) ----------------
__device__ float g_A1[73728 * 75];                 // im2col conv1
__device__ float g_x1[BB * 64 * 24 * 24];          // conv1 out NCHW
__device__ float g_A2[10368 * 576];                // im2col conv2
__device__ float g_x2[BB * 64 * 9 * 9];            // conv2 out NCHW
__device__ float g_A3[2048 * 576];                 // im2col conv3
__device__ float g_x3[BB * 1024];                  // conv3 out flattened [b][1024]
__device__ float g_f1[BB * 1024];
__device__ float g_f2[BB * 512];
__device__ float g_h[2][HH * BB];                  // h transposed [c][b], double buffered
__device__ unsigned int g_count;                   // grid barrier counter (returns to 0)
__device__ unsigned int g_flagv[128 * 32];         // per-CTA monotonic sense flags (128B apart)

// ---------------- im2col conv1: k=5, stride=3, pad=2 ----------------
__global__ void im2col1(const float* __restrict__ img, float* __restrict__ A) {
    int idx = blockIdx.x * 256 + threadIdx.x;
    const int total = 73728 * 75;
    if (idx >= total) return;
    int col = idx % 75, row = idx / 75;
    int ow = row % 24, oh = (row / 24) % 24, n = row / 576;
    int kw = col % 5, kh = (col / 5) % 5, ic = col / 25;
    int ih = oh * 3 - 2 + kh, iw = ow * 3 - 2 + kw;
    float v = 0.f;
    if (ih >= 0 && ih < 72 && iw >= 0 && iw < 72)
        v = img[((size_t)(n * 3 + ic) * 72 + ih) * 72 + iw];
    A[idx] = v;
}

// ---------------- im2col conv2/conv3: k=3, stride=3, pad=2, C=64 ----------------
__global__ void im2col_k3(const float* __restrict__ src, float* __restrict__ A,
                          int IN_H, int OUT_H, int total) {
    int idx = blockIdx.x * 256 + threadIdx.x;
    if (idx >= total) return;
    int col = idx % 576, row = idx / 576;
    int S = OUT_H * OUT_H;
    int s = row % S, n = row / S;
    int ow = s % OUT_H, oh = s / OUT_H;
    int kw = col % 3, kh = (col / 3) % 3, ic = col / 9;
    int ih = oh * 3 - 2 + kh, iw = ow * 3 - 2 + kw;
    float v = 0.f;
    if (ih >= 0 && ih < IN_H && iw >= 0 && iw < IN_H)
        v = src[((size_t)(n * 64 + ic) * IN_H + ih) * IN_H + iw];
    A[idx] = v;
}

// ---------------- tiled GEMM: C = A[M,K] @ Bw[N,K]^T (+bias, relu) ----------------
// (exact known-passing R2 version)
__global__ void gemm64(const float* __restrict__ A, int lda,
                       const float* __restrict__ Bw, int ldb,
                       const float* __restrict__ bias,
                       float* __restrict__ C,
                       int K, int relu, int mode, int S, int ldc) {
    __shared__ float As[16 * 68];
    __shared__ float Bs[16 * 68];
    int tid = threadIdx.x;
    int m0 = blockIdx.x * 64, n0 = blockIdx.y * 64;
    int tx = tid & 15, ty = tid >> 4;
    float acc[4][4] = {};
    int lm = tid >> 2;            // 0..63
    int lk4 = (tid & 3) * 4;      // 0,4,8,12
    for (int kc = 0; kc < K; kc += 16) {
        __syncthreads();
#pragma unroll
        for (int q = 0; q < 4; q++) {
            int k = lk4 + q;
            int gk = kc + k;
            As[k * 68 + lm] = (gk < K) ? A[(size_t)(m0 + lm) * lda + gk] : 0.f;
            Bs[k * 68 + lm] = (gk < K) ? Bw[(size_t)(n0 + lm) * ldb + gk] : 0.f;
        }
        __syncthreads();
#pragma unroll
        for (int k = 0; k < 16; k++) {
            float4 a = *(const float4*)(As + k * 68 + tx * 4);
            float4 b = *(const float4*)(Bs + k * 68 + ty * 4);
            acc[0][0] = fmaf(a.x, b.x, acc[0][0]);
            acc[0][1] = fmaf(a.x, b.y, acc[0][1]);
            acc[0][2] = fmaf(a.x, b.z, acc[0][2]);
            acc[0][3] = fmaf(a.x, b.w, acc[0][3]);
            acc[1][0] = fmaf(a.y, b.x, acc[1][0]);
            acc[1][1] = fmaf(a.y, b.y, acc[1][1]);
            acc[1][2] = fmaf(a.y, b.z, acc[1][2]);
            acc[1][3] = fmaf(a.y, b.w, acc[1][3]);
            acc[2][0] = fmaf(a.z, b.x, acc[2][0]);
            acc[2][1] = fmaf(a.z, b.y, acc[2][1]);
            acc[2][2] = fmaf(a.z, b.z, acc[2][2]);
            acc[2][3] = fmaf(a.z, b.w, acc[2][3]);
            acc[3][0] = fmaf(a.w, b.x, acc[3][0]);
            acc[3][1] = fmaf(a.w, b.y, acc[3][1]);
            acc[3][2] = fmaf(a.w, b.z, acc[3][2]);
            acc[3][3] = fmaf(a.w, b.w, acc[3][3]);
        }
    }
#pragma unroll
    for (int i = 0; i < 4; i++) {
#pragma unroll
        for (int j = 0; j < 4; j++) {
            int r = m0 + tx * 4 + i;
            int c = n0 + ty * 4 + j;
            float v = acc[i][j];
            if (bias) v += bias[c];
            if (relu) v = fmaxf(v, 0.f);
            size_t o;
            if (mode == 0)      o = (size_t)r * ldc + c;
            else if (mode == 1) { int n = r / S, s = r % S; o = ((size_t)(n * ldc + c)) * S + s; }
            else                o = (size_t)c * ldc + r;
            C[o] = v;
        }
    }
}

// ---------------- GRU persistent kernel (512 threads, 4-way K split) ----------------
__device__ __forceinline__ unsigned long long pack2(float x) {
    unsigned long long r;
    asm("mov.b64 %0, {%1, %1};" : "=l"(r) : "f"(x));
    return r;
}
#define FMA2(d, a, b) asm("fma.rn.f32x2 %0, %1, %2, %0;" : "+l"(d) : "l"(a), "l"(b))

__device__ __forceinline__ float sigmoidf_(float x) { return 1.f / (1.f + expf(-x)); }

// dynamic smem (floats): [0,6144) w  | [6144,12288) partials (4 kq x 128 row x 12)
#define GRU_SMEM_BYTES (12288 * 4)

__global__ void __launch_bounds__(512, 1) gru_kernel(
    const float* __restrict__ w_hh, const float* __restrict__ b_hh,
    const float* __restrict__ actions,
    const float* __restrict__ w_ih, const float* __restrict__ b_ih,
    float* __restrict__ out, float* __restrict__ outT) {
    extern __shared__ float dsm[];
    float* wsf = dsm;                                         // 512 k x 12 cols
    unsigned long long* w_u = (unsigned long long*)wsf;       // [k][6 pairs]
    unsigned long long* ghs_u = (unsigned long long*)(dsm + 6144);  // [kq][row][6]
    float* ghs = (float*)ghs_u;
    __shared__ float bhhs[12];
    __shared__ float wihs[12][2];
    __shared__ float bihs[12];
    int tid = threadIdx.x;
    int c0 = blockIdx.x * 4;

    // load w_hh slice resident for all 100 steps:
    // wsf[k*12 + (g*4+ii)] = w_hh[(g*512 + c0+ii)*512 + k]
    for (int i = tid; i < 512 * 12; i += 512) {
        int k = i / 12, j = i % 12;
        int g = j >> 2, ii = j & 3;
        wsf[k * 12 + j] = w_hh[(size_t)(g * 512 + c0 + ii) * 512 + k];
    }
    if (tid < 12) {
        int g = tid >> 2, ii = tid & 3;
        int gr = g * 512 + c0 + ii;
        bhhs[tid] = b_hh[gr];
        bihs[tid] = b_ih[gr];
        wihs[tid][0] = w_ih[gr * 2 + 0];
        wihs[tid][1] = w_ih[gr * 2 + 1];
    }
    __syncthreads();

    int row = tid & 127;      // batch index in matmul phase
    int kq = tid >> 7;        // K quarter 0..3
    int kbase = kq * 128;
    unsigned int* myflag = &g_flagv[blockIdx.x * 32];

    for (int t = 0; t < TT; t++) {
        int rd = t & 1;
        const float* hb = g_h[rd];

        // ---- matmul: partial gh[row][12] over 128 k's, reg double-buffered ----
        unsigned long long a0 = 0, a1 = 0, a2 = 0, a3 = 0, a4 = 0, a5 = 0;
        const unsigned long long* wp = w_u + (size_t)kbase * 6;
        const float* hp = hb + (size_t)kbase * 128 + row;
        float hv[8], hw[8];
#pragma unroll
        for (int j = 0; j < 8; j++) hv[j] = __ldcg(hp + (size_t)j * 128);
        for (int g = 0; g < 16; g++) {
            if (g < 15) {
#pragma unroll
                for (int j = 0; j < 8; j++)
                    hw[j] = __ldcg(hp + (size_t)((g + 1) * 8 + j) * 128);
            }
#pragma unroll
            for (int j = 0; j < 8; j++) {
                int kk = g * 8 + j;
                unsigned long long hh = pack2(hv[j]);
                ulonglong2 w01 = *(const ulonglong2*)(wp + (size_t)kk * 6 + 0);
                ulonglong2 w23 = *(const ulonglong2*)(wp + (size_t)kk * 6 + 2);
                ulonglong2 w45 = *(const ulonglong2*)(wp + (size_t)kk * 6 + 4);
                FMA2(a0, hh, w01.x); FMA2(a1, hh, w01.y);
                FMA2(a2, hh, w23.x); FMA2(a3, hh, w23.y);
                FMA2(a4, hh, w45.x); FMA2(a5, hh, w45.y);
            }
#pragma unroll
            for (int j = 0; j < 8; j++) hv[j] = hw[j];
        }
        {
            unsigned long long* gp = ghs_u + ((size_t)kq * 128 + row) * 6;
            gp[0] = a0; gp[1] = a1; gp[2] = a2; gp[3] = a3; gp[4] = a4; gp[5] = a5;
        }
        __syncthreads();

        // ---- gates: thread (b, ii) handles col c0+ii ----
        {
            int b = tid & 127, ii = tid >> 7;
            int c = c0 + ii;
            float ghr = bhhs[ii], ghz = bhhs[4 + ii], ghn = bhhs[8 + ii];
#pragma unroll
            for (int q = 0; q < 4; q++) {
                const float* gq = ghs + ((size_t)q * 128 + b) * 12;
                ghr += gq[ii];
                ghz += gq[4 + ii];
                ghn += gq[8 + ii];
            }
            float2 act2 = *(const float2*)(actions + ((size_t)b * TT + t) * 2);
            float ir  = fmaf(act2.x, wihs[ii][0],      fmaf(act2.y, wihs[ii][1],      bihs[ii]));
            float iz  = fmaf(act2.x, wihs[4 + ii][0],  fmaf(act2.y, wihs[4 + ii][1],  bihs[4 + ii]));
            float in_ = fmaf(act2.x, wihs[8 + ii][0],  fmaf(act2.y, wihs[8 + ii][1],  bihs[8 + ii]));
            float r = sigmoidf_(ir + ghr);
            float z = sigmoidf_(iz + ghz);
            float n = tanhf(in_ + r * ghn);
            float hprev = __ldcg(hb + (size_t)c * 128 + b);
            float hy = n + z * (hprev - n);
            __stcg(&g_h[1 - rd][(size_t)c * 128 + b], hy);  // coalesced over b
            out[((size_t)b * TT + t) * 512 + c] = hy;
            if (t == TT - 1)
                outT[(size_t)b * 512 + c] = hy;
        }

        // ---- grid barrier: atomic arrive/poll, distributed per-CTA release flags ----
        __threadfence();
        __syncthreads();
        if (tid == 0) {
            unsigned s = atomicAdd(myflag, 0u);                 // my current sense
            unsigned old = atomicAdd(&g_count, 1u);
            if (old == gridDim.x - 1) {
                atomicExch(&g_count, 0u);
                __threadfence();
#pragma unroll 4
                for (int i = 0; i < 128; i++)
                    atomicExch(&g_flagv[i * 32], s + 1u);       // distinct lines: pipelined
            } else {
                while (atomicAdd(myflag, 0u) == s) { }          // private line: no contention
            }
            __threadfence();
        }
        __syncthreads();
    }
}

// ---------------- host ----------------
extern "C" void kernel_launch(void* const* d_in, const int* in_sizes, int n_in,
                              void* d_out, int out_size) {
    const float* images  = (const float*)d_in[0];
    const float* actions = (const float*)d_in[1];
    const float* cw1 = (const float*)d_in[2];
    const float* cb1 = (const float*)d_in[3];
    const float* cw2 = (const float*)d_in[4];
    const float* cb2 = (const float*)d_in[5];
    const float* cw3 = (const float*)d_in[6];
    const float* cb3 = (const float*)d_in[7];
    const float* fw1 = (const float*)d_in[8];
    const float* fb1 = (const float*)d_in[9];
    const float* fw2 = (const float*)d_in[10];
    const float* fb2 = (const float*)d_in[11];
    const float* fw3 = (const float*)d_in[12];
    const float* fb3 = (const float*)d_in[13];
    const float* w_ih = (const float*)d_in[14];
    const float* w_hh = (const float*)d_in[15];
    const float* b_ih = (const float*)d_in[16];
    const float* b_hh = (const float*)d_in[17];
    float* out = (float*)d_out;
    float* outT = out + (size_t)BB * TT * 512;

    float *A1, *x1, *A2, *x2, *A3, *x3, *f1, *f2, *h0;
    cudaGetSymbolAddress((void**)&A1, g_A1);
    cudaGetSymbolAddress((void**)&x1, g_x1);
    cudaGetSymbolAddress((void**)&A2, g_A2);
    cudaGetSymbolAddress((void**)&x2, g_x2);
    cudaGetSymbolAddress((void**)&A3, g_A3);
    cudaGetSymbolAddress((void**)&x3, g_x3);
    cudaGetSymbolAddress((void**)&f1, g_f1);
    cudaGetSymbolAddress((void**)&f2, g_f2);
    cudaGetSymbolAddress((void**)&h0, g_h);   // g_h[0]

    cudaFuncSetAttribute(gru_kernel, cudaFuncAttributeMaxDynamicSharedMemorySize,
                         GRU_SMEM_BYTES);

    // conv1: im2col + GEMM  (M=73728, K=75, N=64) -> NCHW x1
    im2col1<<<21600, 256>>>(images, A1);
    gemm64<<<dim3(1152, 1), 256>>>(A1, 75, cw1, 75, cb1, x1, 75, 1, 1, 576, 64);

    // conv2: (M=10368, K=576, N=64) -> NCHW x2
    im2col_k3<<<23328, 256>>>(x1, A2, 24, 9, 10368 * 576);
    gemm64<<<dim3(162, 1), 256>>>(A2, 576, cw2, 576, cb2, x2, 576, 1, 1, 81, 64);

    // conv3: (M=2048, K=576, N=64) -> flattened x3 [128][1024]
    im2col_k3<<<4608, 256>>>(x2, A3, 9, 4, 2048 * 576);
    gemm64<<<dim3(32, 1), 256>>>(A3, 576, cw3, 576, cb3, x3, 576, 1, 1, 16, 64);

    // fc1: [128,1024] @ fw1[1024,1024]^T, relu
    gemm64<<<dim3(2, 16), 256>>>(x3, 1024, fw1, 1024, fb1, f1, 1024, 1, 0, 0, 1024);
    // fc2: [128,1024] @ fw2[512,1024]^T, relu
    gemm64<<<dim3(2, 8), 256>>>(f1, 1024, fw2, 1024, fb2, f2, 1024, 1, 0, 0, 512);
    // fc3: [128,512] @ fw3[512,512]^T -> h0 transposed [c][b]
    gemm64<<<dim3(2, 8), 256>>>(f2, 512, fw3, 512, fb3, h0, 512, 0, 2, 0, 128);

    // GRU: 128 persistent CTAs, 512 threads, 100 steps with internal grid barrier
    gru_kernel<<<128, 512, GRU_SMEM_BYTES>>>(w_hh, b_hh, actions, w_ih, b_ih, out, outT);
}

// round 16
// speedup vs baseline: 2.2693x; 2.2693x over previous
#include <cuda_runtime.h>

#define BB 128
#define TT 100
#define HH 512

// ---------------- scratch (device globals; no runtime alloc) ----------------
__device__ float g_A1[73728 * 75];                 // im2col conv1
__device__ float g_x1[BB * 64 * 24 * 24];          // conv1 out NCHW
__device__ float g_A2[10368 * 576];                // im2col conv2
__device__ float g_x2[BB * 64 * 9 * 9];            // conv2 out NCHW
__device__ float g_A3[2048 * 576];                 // im2col conv3
__device__ float g_x3[BB * 1024];                  // conv3 out flattened [b][1024]
__device__ float g_f1[BB * 1024];
__device__ float g_f2[BB * 512];
__device__ float g_h[2][HH * BB];                  // h transposed [c][b], double buffered
__device__ unsigned int g_count;                   // grid barrier counter (returns to 0)
__device__ unsigned int g_sense;                   // monotonic phase counter (replay-safe)

// ---------------- im2col conv1: k=5, stride=3, pad=2 ----------------
__global__ void im2col1(const float* __restrict__ img, float* __restrict__ A) {
    int idx = blockIdx.x * 256 + threadIdx.x;
    const int total = 73728 * 75;
    if (idx >= total) return;
    int col = idx % 75, row = idx / 75;
    int ow = row % 24, oh = (row / 24) % 24, n = row / 576;
    int kw = col % 5, kh = (col / 5) % 5, ic = col / 25;
    int ih = oh * 3 - 2 + kh, iw = ow * 3 - 2 + kw;
    float v = 0.f;
    if (ih >= 0 && ih < 72 && iw >= 0 && iw < 72)
        v = img[((size_t)(n * 3 + ic) * 72 + ih) * 72 + iw];
    A[idx] = v;
}

// ---------------- im2col conv2/conv3: k=3, stride=3, pad=2, C=64 ----------------
__global__ void im2col_k3(const float* __restrict__ src, float* __restrict__ A,
                          int IN_H, int OUT_H, int total) {
    int idx = blockIdx.x * 256 + threadIdx.x;
    if (idx >= total) return;
    int col = idx % 576, row = idx / 576;
    int S = OUT_H * OUT_H;
    int s = row % S, n = row / S;
    int ow = s % OUT_H, oh = s / OUT_H;
    int kw = col % 3, kh = (col / 3) % 3, ic = col / 9;
    int ih = oh * 3 - 2 + kh, iw = ow * 3 - 2 + kw;
    float v = 0.f;
    if (ih >= 0 && ih < IN_H && iw >= 0 && iw < IN_H)
        v = src[((size_t)(n * 64 + ic) * IN_H + ih) * IN_H + iw];
    A[idx] = v;
}

// ---------------- tiled GEMM: C = A[M,K] @ Bw[N,K]^T (+bias, relu) ----------------
// Register-prefetch pipeline: chunk k+1 LDGs issue during chunk k's FMAs.
// Thread-local change only; identical addresses and accumulation order.
// mode 0: C[r*ldc + c]                         (row-major)
// mode 1: C[((r/S)*ldc + c)*S + (r%S)]         (NCHW scatter, ldc = OC)
// mode 2: C[c*ldc + r]                         (transposed, ldc = 128) -> h0^T
__global__ void gemm64(const float* __restrict__ A, int lda,
                       const float* __restrict__ Bw, int ldb,
                       const float* __restrict__ bias,
                       float* __restrict__ C,
                       int K, int relu, int mode, int S, int ldc) {
    __shared__ float As[16 * 68];
    __shared__ float Bs[16 * 68];
    int tid = threadIdx.x;
    int m0 = blockIdx.x * 64, n0 = blockIdx.y * 64;
    int tx = tid & 15, ty = tid >> 4;
    float acc[4][4] = {};
    int lm = tid >> 2;            // 0..63
    int lk4 = (tid & 3) * 4;      // 0,4,8,12
    float rA[4], rB[4];

#pragma unroll
    for (int q = 0; q < 4; q++) {
        int gk = lk4 + q;
        rA[q] = (gk < K) ? A[(size_t)(m0 + lm) * lda + gk] : 0.f;
        rB[q] = (gk < K) ? Bw[(size_t)(n0 + lm) * ldb + gk] : 0.f;
    }
    for (int kc = 0; kc < K; kc += 16) {
#pragma unroll
        for (int q = 0; q < 4; q++) {
            As[(lk4 + q) * 68 + lm] = rA[q];
            Bs[(lk4 + q) * 68 + lm] = rB[q];
        }
        __syncthreads();
        if (kc + 16 < K) {
#pragma unroll
            for (int q = 0; q < 4; q++) {
                int gk = kc + 16 + lk4 + q;
                rA[q] = (gk < K) ? A[(size_t)(m0 + lm) * lda + gk] : 0.f;
                rB[q] = (gk < K) ? Bw[(size_t)(n0 + lm) * ldb + gk] : 0.f;
            }
        }
#pragma unroll
        for (int k = 0; k < 16; k++) {
            float4 a = *(const float4*)(As + k * 68 + tx * 4);
            float4 b = *(const float4*)(Bs + k * 68 + ty * 4);
            acc[0][0] = fmaf(a.x, b.x, acc[0][0]);
            acc[0][1] = fmaf(a.x, b.y, acc[0][1]);
            acc[0][2] = fmaf(a.x, b.z, acc[0][2]);
            acc[0][3] = fmaf(a.x, b.w, acc[0][3]);
            acc[1][0] = fmaf(a.y, b.x, acc[1][0]);
            acc[1][1] = fmaf(a.y, b.y, acc[1][1]);
            acc[1][2] = fmaf(a.y, b.z, acc[1][2]);
            acc[1][3] = fmaf(a.y, b.w, acc[1][3]);
            acc[2][0] = fmaf(a.z, b.x, acc[2][0]);
            acc[2][1] = fmaf(a.z, b.y, acc[2][1]);
            acc[2][2] = fmaf(a.z, b.z, acc[2][2]);
            acc[2][3] = fmaf(a.z, b.w, acc[2][3]);
            acc[3][0] = fmaf(a.w, b.x, acc[3][0]);
            acc[3][1] = fmaf(a.w, b.y, acc[3][1]);
            acc[3][2] = fmaf(a.w, b.z, acc[3][2]);
            acc[3][3] = fmaf(a.w, b.w, acc[3][3]);
        }
        __syncthreads();
    }
#pragma unroll
    for (int i = 0; i < 4; i++) {
#pragma unroll
        for (int j = 0; j < 4; j++) {
            int r = m0 + tx * 4 + i;
            int c = n0 + ty * 4 + j;
            float v = acc[i][j];
            if (bias) v += bias[c];
            if (relu) v = fmaxf(v, 0.f);
            size_t o;
            if (mode == 0)      o = (size_t)r * ldc + c;
            else if (mode == 1) { int n = r / S, s = r % S; o = ((size_t)(n * ldc + c)) * S + s; }
            else                o = (size_t)c * ldc + r;
            C[o] = v;
        }
    }
}

// ---------------- GRU persistent kernel (EXACT R13: 512 threads, 4-way K split) ----------------
__device__ __forceinline__ unsigned long long pack2(float x) {
    unsigned long long r;
    asm("mov.b64 %0, {%1, %1};" : "=l"(r) : "f"(x));
    return r;
}
#define FMA2(d, a, b) asm("fma.rn.f32x2 %0, %1, %2, %0;" : "+l"(d) : "l"(a), "l"(b))

__device__ __forceinline__ float sigmoidf_(float x) { return 1.f / (1.f + expf(-x)); }

// dynamic smem (floats): [0,6144) w  | [6144,12288) partials (4 kq x 128 row x 12)
#define GRU_SMEM_BYTES (12288 * 4)

__global__ void __launch_bounds__(512, 1) gru_kernel(
    const float* __restrict__ w_hh, const float* __restrict__ b_hh,
    const float* __restrict__ actions,
    const float* __restrict__ w_ih, const float* __restrict__ b_ih,
    float* __restrict__ out, float* __restrict__ outT) {
    extern __shared__ float dsm[];
    float* wsf = dsm;                                         // 512 k x 12 cols
    unsigned long long* w_u = (unsigned long long*)wsf;       // [k][6 pairs]
    unsigned long long* ghs_u = (unsigned long long*)(dsm + 6144);  // [kq][row][6]
    float* ghs = (float*)ghs_u;
    __shared__ float bhhs[12];
    __shared__ float wihs[12][2];
    __shared__ float bihs[12];
    int tid = threadIdx.x;
    int c0 = blockIdx.x * 4;

    // load w_hh slice resident for all 100 steps:
    // wsf[k*12 + (g*4+ii)] = w_hh[(g*512 + c0+ii)*512 + k]
    for (int i = tid; i < 512 * 12; i += 512) {
        int k = i / 12, j = i % 12;
        int g = j >> 2, ii = j & 3;
        wsf[k * 12 + j] = w_hh[(size_t)(g * 512 + c0 + ii) * 512 + k];
    }
    if (tid < 12) {
        int g = tid >> 2, ii = tid & 3;
        int gr = g * 512 + c0 + ii;
        bhhs[tid] = b_hh[gr];
        bihs[tid] = b_ih[gr];
        wihs[tid][0] = w_ih[gr * 2 + 0];
        wihs[tid][1] = w_ih[gr * 2 + 1];
    }
    __syncthreads();

    int row = tid & 127;      // batch index in matmul phase
    int kq = tid >> 7;        // K quarter 0..3
    int kbase = kq * 128;

    for (int t = 0; t < TT; t++) {
        int rd = t & 1;
        const float* hb = g_h[rd];

        // ---- matmul: partial gh[row][12] over 128 k's, reg double-buffered ----
        unsigned long long a0 = 0, a1 = 0, a2 = 0, a3 = 0, a4 = 0, a5 = 0;
        const unsigned long long* wp = w_u + (size_t)kbase * 6;
        const float* hp = hb + (size_t)kbase * 128 + row;
        float hv[8], hw[8];
#pragma unroll
        for (int j = 0; j < 8; j++) hv[j] = __ldcg(hp + (size_t)j * 128);
        for (int g = 0; g < 16; g++) {
            if (g < 15) {
#pragma unroll
                for (int j = 0; j < 8; j++)
                    hw[j] = __ldcg(hp + (size_t)((g + 1) * 8 + j) * 128);
            }
#pragma unroll
            for (int j = 0; j < 8; j++) {
                int kk = g * 8 + j;
                unsigned long long hh = pack2(hv[j]);
                ulonglong2 w01 = *(const ulonglong2*)(wp + (size_t)kk * 6 + 0);
                ulonglong2 w23 = *(const ulonglong2*)(wp + (size_t)kk * 6 + 2);
                ulonglong2 w45 = *(const ulonglong2*)(wp + (size_t)kk * 6 + 4);
                FMA2(a0, hh, w01.x); FMA2(a1, hh, w01.y);
                FMA2(a2, hh, w23.x); FMA2(a3, hh, w23.y);
                FMA2(a4, hh, w45.x); FMA2(a5, hh, w45.y);
            }
#pragma unroll
            for (int j = 0; j < 8; j++) hv[j] = hw[j];
        }
        {
            unsigned long long* gp = ghs_u + ((size_t)kq * 128 + row) * 6;
            gp[0] = a0; gp[1] = a1; gp[2] = a2; gp[3] = a3; gp[4] = a4; gp[5] = a5;
        }
        __syncthreads();

        // ---- gates: thread (b, ii) handles col c0+ii ----
        {
            int b = tid & 127, ii = tid >> 7;
            int c = c0 + ii;
            float ghr = bhhs[ii], ghz = bhhs[4 + ii], ghn = bhhs[8 + ii];
#pragma unroll
            for (int q = 0; q < 4; q++) {
                const float* gq = ghs + ((size_t)q * 128 + b) * 12;
                ghr += gq[ii];
                ghz += gq[4 + ii];
                ghn += gq[8 + ii];
            }
            float2 act2 = *(const float2*)(actions + ((size_t)b * TT + t) * 2);
            float ir  = fmaf(act2.x, wihs[ii][0],      fmaf(act2.y, wihs[ii][1],      bihs[ii]));
            float iz  = fmaf(act2.x, wihs[4 + ii][0],  fmaf(act2.y, wihs[4 + ii][1],  bihs[4 + ii]));
            float in_ = fmaf(act2.x, wihs[8 + ii][0],  fmaf(act2.y, wihs[8 + ii][1],  bihs[8 + ii]));
            float r = sigmoidf_(ir + ghr);
            float z = sigmoidf_(iz + ghz);
            float n = tanhf(in_ + r * ghn);
            float hprev = __ldcg(hb + (size_t)c * 128 + b);
            float hy = n + z * (hprev - n);
            __stcg(&g_h[1 - rd][(size_t)c * 128 + b], hy);  // coalesced over b
            out[((size_t)b * TT + t) * 512 + c] = hy;
            if (t == TT - 1)
                outT[(size_t)b * 512 + c] = hy;
        }

        // ---- grid barrier (EXACT R13 protocol: shared sense, all-atomic) ----
        __threadfence();
        __syncthreads();
        if (tid == 0) {
            unsigned s = atomicAdd(&g_sense, 0u);
            unsigned old = atomicAdd(&g_count, 1u);
            if (old == gridDim.x - 1) {
                atomicExch(&g_count, 0u);
                __threadfence();
                atomicExch(&g_sense, s + 1u);
            } else {
                while (atomicAdd(&g_sense, 0u) == s) { }
            }
            __threadfence();
        }
        __syncthreads();
    }
}

// ---------------- host ----------------
extern "C" void kernel_launch(void* const* d_in, const int* in_sizes, int n_in,
                              void* d_out, int out_size) {
    const float* images  = (const float*)d_in[0];
    const float* actions = (const float*)d_in[1];
    const float* cw1 = (const float*)d_in[2];
    const float* cb1 = (const float*)d_in[3];
    const float* cw2 = (const float*)d_in[4];
    const float* cb2 = (const float*)d_in[5];
    const float* cw3 = (const float*)d_in[6];
    const float* cb3 = (const float*)d_in[7];
    const float* fw1 = (const float*)d_in[8];
    const float* fb1 = (const float*)d_in[9];
    const float* fw2 = (const float*)d_in[10];
    const float* fb2 = (const float*)d_in[11];
    const float* fw3 = (const float*)d_in[12];
    const float* fb3 = (const float*)d_in[13];
    const float* w_ih = (const float*)d_in[14];
    const float* w_hh = (const float*)d_in[15];
    const float* b_ih = (const float*)d_in[16];
    const float* b_hh = (const float*)d_in[17];
    float* out = (float*)d_out;
    float* outT = out + (size_t)BB * TT * 512;

    float *A1, *x1, *A2, *x2, *A3, *x3, *f1, *f2, *h0;
    cudaGetSymbolAddress((void**)&A1, g_A1);
    cudaGetSymbolAddress((void**)&x1, g_x1);
    cudaGetSymbolAddress((void**)&A2, g_A2);
    cudaGetSymbolAddress((void**)&x2, g_x2);
    cudaGetSymbolAddress((void**)&A3, g_A3);
    cudaGetSymbolAddress((void**)&x3, g_x3);
    cudaGetSymbolAddress((void**)&f1, g_f1);
    cudaGetSymbolAddress((void**)&f2, g_f2);
    cudaGetSymbolAddress((void**)&h0, g_h);   // g_h[0]

    cudaFuncSetAttribute(gru_kernel, cudaFuncAttributeMaxDynamicSharedMemorySize,
                         GRU_SMEM_BYTES);

    // conv1: im2col + GEMM  (M=73728, K=75, N=64) -> NCHW x1
    im2col1<<<21600, 256>>>(images, A1);
    gemm64<<<dim3(1152, 1), 256>>>(A1, 75, cw1, 75, cb1, x1, 75, 1, 1, 576, 64);

    // conv2: (M=10368, K=576, N=64) -> NCHW x2
    im2col_k3<<<23328, 256>>>(x1, A2, 24, 9, 10368 * 576);
    gemm64<<<dim3(162, 1), 256>>>(A2, 576, cw2, 576, cb2, x2, 576, 1, 1, 81, 64);

    // conv3: (M=2048, K=576, N=64) -> flattened x3 [128][1024]
    im2col_k3<<<4608, 256>>>(x2, A3, 9, 4, 2048 * 576);
    gemm64<<<dim3(32, 1), 256>>>(A3, 576, cw3, 576, cb3, x3, 576, 1, 1, 16, 64);

    // fc1: [128,1024] @ fw1[1024,1024]^T, relu
    gemm64<<<dim3(2, 16), 256>>>(x3, 1024, fw1, 1024, fb1, f1, 1024, 1, 0, 0, 1024);
    // fc2: [128,1024] @ fw2[512,1024]^T, relu
    gemm64<<<dim3(2, 8), 256>>>(f1, 1024, fw2, 1024, fb2, f2, 1024, 1, 0, 0, 512);
    // fc3: [128,512] @ fw3[512,512]^T -> h0 transposed [c][b]
    gemm64<<<dim3(2, 8), 256>>>(f2, 512, fw3, 512, fb3, h0, 512, 0, 2, 0, 128);

    // GRU: 128 persistent CTAs, 512 threads, 100 steps with internal grid barrier
    gru_kernel<<<128, 512, GRU_SMEM_BYTES>>>(w_hh, b_hh, actions, w_ih, b_ih, out, outT);
}